// round 15
// baseline (speedup 1.0000x reference)
#include <cuda_runtime.h>
#include <math.h>

#define Bv 8
#define Tv 4096
#define Dv 1024
#define EPS 0.01f
#define TT 64                  // timesteps per block
#define TILES (Tv / TT)        // 64
#define LOG2_C (-0.014499569695115089f)   // log2(0.99)

// Device scratch — 16B-aligned (accessed through float4 casts)
__device__ __align__(16) float d_y[Bv * Tv];                       // x_t . w
__device__ __align__(16) float d_mempart[(size_t)Bv * TILES * Dv]; // FINAL-scaled partials
__device__ int d_count[Bv];    // arrivals; 0 at load, reset by last block each launch

// ---------------------------------------------------------------------------
// Epilogue for one batch — __noinline__ so ptxas schedules the hot streaming
// loop independently (round-12 regression root cause: inlined cold code
// reshaped the hot loop's register staging and broke 8-deep load batching).
// ---------------------------------------------------------------------------
__device__ __noinline__ void epilogue_for_batch(int b,
                                                const int* __restrict__ pad,
                                                const int* __restrict__ upd,
                                                float* __restrict__ out) {
    const int tid = threadIdx.x;
    const int warp = tid >> 5;
    const int lane = tid & 31;

    __shared__ float sWA[8], sWC[8], sWAe[8];

    // ---- scan: u_t = c_t*u_{t-1} + eps*g_t*y_t -> bias --------------------
    unsigned gmask = 0, pmask = 0;
    float yv[16];
    {
        const int4* p4 = (const int4*)(pad + b * Tv);
        const int4* u4 = (const int4*)(upd + b * Tv);
#pragma unroll
        for (int q = 0; q < 4; q++) {
            int4 a = __ldg(&p4[tid * 4 + q]);
            int4 c = __ldg(&u4[tid * 4 + q]);
            int pa[4] = {a.x, a.y, a.z, a.w};
            int ua[4] = {c.x, c.y, c.z, c.w};
            float4 yq = __ldcg((const float4*)&d_y[b * Tv + tid * 16 + q * 4]);
            float ya[4] = {yq.x, yq.y, yq.z, yq.w};
#pragma unroll
            for (int r = 0; r < 4; r++) {
                int k = q * 4 + r;
                if (pa[r] != 0) pmask |= (1u << k);
                if (pa[r] == 0 && ua[r] != 0) gmask |= (1u << k);
                yv[k] = ya[r];
            }
        }
    }

    float C = 1.f, A = 0.f;
#pragma unroll
    for (int k = 0; k < 16; k++) {
        if ((gmask >> k) & 1u) { A = 0.99f * A + 0.01f * yv[k]; C *= 0.99f; }
    }
#pragma unroll
    for (int off = 1; off < 32; off <<= 1) {
        float pC = __shfl_up_sync(0xffffffffu, C, off);
        float pA = __shfl_up_sync(0xffffffffu, A, off);
        float nA = fmaf(C, pA, A);
        float nC = C * pC;
        if (lane >= off) { A = nA; C = nC; }
    }
    float eC = __shfl_up_sync(0xffffffffu, C, 1);
    float eA = __shfl_up_sync(0xffffffffu, A, 1);
    if (lane == 0) { eC = 1.f; eA = 0.f; }
    if (lane == 31) { sWC[warp] = C; sWA[warp] = A; }
    __syncthreads();
    if (tid == 0) {
        float c = 1.f, a = 0.f;
#pragma unroll
        for (int ww = 0; ww < 8; ww++) {
            sWAe[ww] = a;
            float na = fmaf(sWC[ww], a, sWA[ww]);
            c = sWC[ww] * c; a = na;
        }
    }
    __syncthreads();

    float u = fmaf(eC, sWAe[warp], eA);
    float4* o4 = (float4*)(out + b * Tv + tid * 16);
#pragma unroll
    for (int q = 0; q < 4; q++) {
        float ob[4];
#pragma unroll
        for (int r = 0; r < 4; r++) {
            int k = q * 4 + r;
            if ((gmask >> k) & 1u) u = fmaf(0.99f, u, 0.01f * yv[k]);
            if ((pmask >> k) & 1u) {
                ob[r] = 1.0f;
            } else {
                // 1 + tanh(u) = 2 / (1 + e^(-2u)); MUFU path, rel err ~1e-6
                float bb = __fdividef(2.0f, 1.0f + __expf(-2.0f * u));
                ob[r] = fminf(fmaxf(bb, 0.8f), 1.2f);
            }
        }
        o4[q] = make_float4(ob[0], ob[1], ob[2], ob[3]);
    }

    // ---- memred: plain fixed-order sum (partials already final-scaled) ----
    {
        const float4* mp4 = (const float4*)&d_mempart[(size_t)b * TILES * Dv];
        float4 s = make_float4(0.f, 0.f, 0.f, 0.f);
#pragma unroll 1
        for (int t8 = 0; t8 < TILES; t8 += 8) {
            float4 v[8];
#pragma unroll
            for (int j = 0; j < 8; j++)
                v[j] = __ldcg(&mp4[(size_t)(t8 + j) * 256 + tid]);
#pragma unroll
            for (int j = 0; j < 8; j++) {
                s.x += v[j].x; s.y += v[j].y; s.z += v[j].z; s.w += v[j].w;
            }
        }
        ((float4*)(out + Bv * Tv + b * Dv))[tid] = s;
    }

    // ---- counter reset for next graph replay -----------------------------
    __syncthreads();
    if (tid == 0) atomicExch(&d_count[b], 0);
}

// ---------------------------------------------------------------------------
// Fused kernel: round-13 main (suffix-scaled coefficients + round-9 hot loop)
// + last-block-per-batch epilogue behind a __noinline__ call.
// grid (TILES, Bv) = 512 blocks, single wave at 4 blocks/SM. Last block never
// waits on anyone -> no deadlock; epilogue depends only on b -> deterministic.
// ---------------------------------------------------------------------------
__global__ void __launch_bounds__(256, 4) fused_kernel(const float* __restrict__ x,
                                                       const float* __restrict__ w,
                                                       const int* __restrict__ pad,
                                                       const int* __restrict__ upd,
                                                       float* __restrict__ out) {
    const int b = blockIdx.y;
    const int t0 = blockIdx.x * TT;
    const int tid = threadIdx.x;
    const int warp = tid >> 5;
    const int lane = tid & 31;

    __shared__ __align__(16) float s_coef[TT];
    __shared__ float s_pdot[TT * 8];     // [row][warp]
    __shared__ unsigned s_mask[2];
    __shared__ int s_wcnt[8];
    __shared__ int s_suffix;
    __shared__ int s_last;

    // ---- suffix gate count over t in [t0+TT, Tv) --------------------------
    {
        int cnt = 0;
        const int4* p4 = (const int4*)(pad + b * Tv);
        const int4* u4 = (const int4*)(upd + b * Tv);
        for (int i4 = ((t0 + TT) >> 2) + tid; i4 < (Tv >> 2); i4 += 256) {
            int4 a = __ldg(&p4[i4]);
            int4 c = __ldg(&u4[i4]);
            cnt += (a.x == 0 && c.x != 0) + (a.y == 0 && c.y != 0)
                 + (a.z == 0 && c.z != 0) + (a.w == 0 && c.w != 0);
        }
#pragma unroll
        for (int off = 16; off; off >>= 1)
            cnt += __shfl_down_sync(0xffffffffu, cnt, off);
        if (lane == 0) s_wcnt[warp] = cnt;
    }
    // ---- gate bits for this tile ------------------------------------------
    if (tid < 64) {
        int t = t0 + tid;
        bool g = (pad[b * Tv + t] == 0) && (upd[b * Tv + t] != 0);
        unsigned bal = __ballot_sync(0xffffffffu, g);
        if ((tid & 31) == 0) s_mask[tid >> 5] = bal;
    }
    __syncthreads();
    if (tid == 0) {
        int s = 0;
#pragma unroll
        for (int ww = 0; ww < 8; ww++) s += s_wcnt[ww];
        s_suffix = s;
    }
    __syncthreads();
    if (tid < 64) {
        unsigned m0 = s_mask[0], m1 = s_mask[1];
        int lt = tid & 31;
        bool g; int cnt;
        if (tid < 32) {
            g = (m0 >> lt) & 1u;
            unsigned hi = (lt == 31) ? 0u : (m0 >> (lt + 1));
            cnt = __popc(hi) + __popc(m1);
        } else {
            g = (m1 >> lt) & 1u;
            unsigned hi = (lt == 31) ? 0u : (m1 >> (lt + 1));
            cnt = __popc(hi);
        }
        // GLOBAL coefficient: eps * 0.99^(all gates after t)
        s_coef[tid] = g ? (EPS * exp2f((float)(cnt + s_suffix) * LOG2_C)) : 0.0f;
    }
    __syncthreads();

    // ---- streaming loop (round-9 verbatim) ---------------------------------
    const int d4 = warp * 32 + lane;                 // float4 index in D (0..255)
    const float4 wv = __ldg(&((const float4*)w)[d4]);
    float4 macc = make_float4(0.f, 0.f, 0.f, 0.f);
    const float4* xb = (const float4*)(x + ((size_t)(b * Tv + t0)) * Dv) + d4;

#pragma unroll 1
    for (int rr = 0; rr < TT; rr += 8) {
        // phase 1: 8 independent loads, no consumers in between (MLP_p1 = 8)
        float4 v[8];
#pragma unroll
        for (int j = 0; j < 8; j++)
            v[j] = __ldcs(xb + (size_t)(rr + j) * 256);

        // phase 2: dots + weighted accumulate + warp reduce
#pragma unroll
        for (int j = 0; j < 8; j++) {
            const float c = s_coef[rr + j];
            float dot = v[j].x * wv.x + v[j].y * wv.y + v[j].z * wv.z + v[j].w * wv.w;
            macc.x = fmaf(c, v[j].x, macc.x);
            macc.y = fmaf(c, v[j].y, macc.y);
            macc.z = fmaf(c, v[j].z, macc.z);
            macc.w = fmaf(c, v[j].w, macc.w);
#pragma unroll
            for (int off = 16; off; off >>= 1)
                dot += __shfl_down_sync(0xffffffffu, dot, off);
            if (lane == 0) s_pdot[(rr + j) * 8 + warp] = dot;
        }
    }
    __syncthreads();

    // finish dots: 64 threads, fixed-order 8-way sums (deterministic)
    if (tid < TT) {
        float s = 0.f;
#pragma unroll
        for (int ww = 0; ww < 8; ww++) s += s_pdot[tid * 8 + ww];
        d_y[b * Tv + t0 + tid] = s;
    }

    // final-scaled per-tile partial (each thread owns its float4 of D)
    ((float4*)&d_mempart[((size_t)b * TILES + blockIdx.x) * Dv])[d4] = macc;

    // ---- last-block fence ---------------------------------------------------
    __threadfence();
    __syncthreads();
    if (tid == 0) {
        int old = atomicAdd(&d_count[b], 1);
        s_last = (old == TILES - 1);
    }
    __syncthreads();
    if (!s_last) return;
    __threadfence();   // acquire: all tiles' d_y / d_mempart visible

    epilogue_for_batch(b, pad, upd, out);
}

// ---------------------------------------------------------------------------
extern "C" void kernel_launch(void* const* d_in, const int* in_sizes, int n_in,
                              void* d_out, int out_size) {
    const float* x = (const float*)d_in[0];            // write_signal (8,4096,1024)
    const int* pad = (const int*)d_in[1];              // pad_mask bool -> int32 (8,4096)
    const int* upd = (const int*)d_in[2];              // update_mask bool -> int32 (8,4096)
    const float* w = (const float*)d_in[3];            // w (1024,)
    float* out = (float*)d_out;                        // [bias (8*4096) | memory (8*1024)]

    dim3 grid(TILES, Bv);   // 512 blocks, single wave at 4 blocks/SM
    fused_kernel<<<grid, 256>>>(x, w, pad, upd, out);
}

// round 17
// speedup vs baseline: 2.1004x; 2.1004x over previous
#include <cuda_runtime.h>
#include <math.h>

#define Bv 8
#define Tv 4096
#define Dv 1024
#define EPS 0.01f
#define TT 64                  // timesteps per block
#define TILES (Tv / TT)        // 64
#define LOG2_C (-0.014499569695115089f)   // log2(0.99)

// Device scratch — 16B-aligned (accessed through float4 casts)
__device__ __align__(16) float d_y[Bv * Tv];                       // x_t . w (gated rows only)
__device__ __align__(16) float d_mempart[(size_t)Bv * TILES * Dv]; // FINAL-scaled partials

// ---------------------------------------------------------------------------
// Main pass: ONLY GATED ROWS ARE LOADED (~25% of x). gate rows compacted via
// ballot ranks; coefficients carry the full global decay (suffix gate count),
// so mempart needs only a plain sum downstream.
// ---------------------------------------------------------------------------
__global__ void __launch_bounds__(256, 4) main_kernel(const float* __restrict__ x,
                                                      const float* __restrict__ w,
                                                      const int* __restrict__ pad,
                                                      const int* __restrict__ upd) {
    const int b = blockIdx.y;
    const int t0 = blockIdx.x * TT;
    const int tid = threadIdx.x;
    const int warp = tid >> 5;
    const int lane = tid & 31;

    __shared__ __align__(16) float s_coef[TT];
    __shared__ float s_pdot[TT * 8];     // [row][warp]
    __shared__ unsigned s_mask[2];
    __shared__ int s_wcnt[8];
    __shared__ int s_suffix;
    // ALIGNMENT: read below as uint2 (LDS.64) -> must be 8B-aligned.
    // (Round-16 trap: unsigned char[] has 1B alignment by default.)
    __shared__ __align__(8) unsigned char s_rows[TT]; // compacted gated row ids
    __shared__ int s_n;                  // number of gated rows

    // ---- suffix gate count over t in [t0+TT, Tv) (L2-resident masks) ------
    {
        int cnt = 0;
        const int4* p4 = (const int4*)(pad + b * Tv);
        const int4* u4 = (const int4*)(upd + b * Tv);
        for (int i4 = ((t0 + TT) >> 2) + tid; i4 < (Tv >> 2); i4 += 256) {
            int4 a = __ldg(&p4[i4]);
            int4 c = __ldg(&u4[i4]);
            cnt += (a.x == 0 && c.x != 0) + (a.y == 0 && c.y != 0)
                 + (a.z == 0 && c.z != 0) + (a.w == 0 && c.w != 0);
        }
#pragma unroll
        for (int off = 16; off; off >>= 1)
            cnt += __shfl_down_sync(0xffffffffu, cnt, off);
        if (lane == 0) s_wcnt[warp] = cnt;
    }
    // ---- gate bits for this tile -------------------------------------------
    if (tid < 64) {
        s_rows[tid] = 0;   // padding rows load row 0 (valid addr) at c=0
        int t = t0 + tid;
        bool g = (pad[b * Tv + t] == 0) && (upd[b * Tv + t] != 0);
        unsigned bal = __ballot_sync(0xffffffffu, g);
        if ((tid & 31) == 0) s_mask[tid >> 5] = bal;
    }
    __syncthreads();
    if (tid == 0) {
        int s = 0;
#pragma unroll
        for (int ww = 0; ww < 8; ww++) s += s_wcnt[ww];
        s_suffix = s;
    }
    __syncthreads();
    if (tid < 64) {
        unsigned m0 = s_mask[0], m1 = s_mask[1];
        int lt = tid & 31;
        bool g; int cnt; int rank;
        if (tid < 32) {
            g = (m0 >> lt) & 1u;
            unsigned hi = (lt == 31) ? 0u : (m0 >> (lt + 1));
            cnt = __popc(hi) + __popc(m1);
            rank = __popc(m0 & ((1u << lt) - 1u));
        } else {
            g = (m1 >> lt) & 1u;
            unsigned hi = (lt == 31) ? 0u : (m1 >> (lt + 1));
            cnt = __popc(hi);
            rank = __popc(m0) + __popc(m1 & ((1u << lt) - 1u));
        }
        // GLOBAL coefficient: eps * 0.99^(all gates after t)
        s_coef[tid] = g ? (EPS * exp2f((float)(cnt + s_suffix) * LOG2_C)) : 0.0f;
        if (g) s_rows[rank] = (unsigned char)tid;
        if (tid == 0) s_n = __popc(m0) + __popc(m1);
    }
    __syncthreads();

    // ---- streaming loop: ONLY compacted gated rows ---------------------------
    const int n = s_n;                               // ~16 expected
    const int d4 = warp * 32 + lane;                 // float4 index in D (0..255)
    const float4 wv = __ldg(&((const float4*)w)[d4]);
    float4 macc = make_float4(0.f, 0.f, 0.f, 0.f);
    const float4* xb = (const float4*)(x + ((size_t)(b * Tv + t0)) * Dv) + d4;

#pragma unroll 1
    for (int i = 0; i < n; i += 8) {
        // row ids for this chunk (8 bytes = one LDS.64); pad slots hold row 0
        int rows[8];
        {
            uint2 rr = *(const uint2*)&s_rows[i];    // i multiple of 8; base 8B-aligned
#pragma unroll
            for (int j = 0; j < 4; j++) rows[j] = (rr.x >> (8 * j)) & 0xFF;
#pragma unroll
            for (int j = 0; j < 4; j++) rows[4 + j] = (rr.y >> (8 * j)) & 0xFF;
        }
        // phase 1: 8 independent loads (pad slots duplicate row 0 -> L1 hits)
        float4 v[8];
#pragma unroll
        for (int j = 0; j < 8; j++)
            v[j] = __ldcs(xb + (size_t)rows[j] * 256);

        // phase 2: dots + weighted accumulate + warp reduce
#pragma unroll
        for (int j = 0; j < 8; j++) {
            const bool live = (i + j) < n;
            const float c = live ? s_coef[rows[j]] : 0.0f;
            float dot = v[j].x * wv.x + v[j].y * wv.y + v[j].z * wv.z + v[j].w * wv.w;
            macc.x = fmaf(c, v[j].x, macc.x);
            macc.y = fmaf(c, v[j].y, macc.y);
            macc.z = fmaf(c, v[j].z, macc.z);
            macc.w = fmaf(c, v[j].w, macc.w);
#pragma unroll
            for (int off = 16; off; off >>= 1)
                dot += __shfl_down_sync(0xffffffffu, dot, off);
            if (lane == 0 && live) s_pdot[rows[j] * 8 + warp] = dot;
        }
    }
    __syncthreads();

    // finish dots for GATED rows only (ungated d_y never read in arithmetic)
    if (tid < TT && s_coef[tid] != 0.0f) {
        float s = 0.f;
#pragma unroll
        for (int ww = 0; ww < 8; ww++) s += s_pdot[tid * 8 + ww];
        d_y[b * Tv + t0 + tid] = s;
    }

    // final-scaled per-tile partial (each thread owns its float4 of D)
    ((float4*)&d_mempart[((size_t)b * TILES + blockIdx.x) * Dv])[d4] = macc;
}

// ---------------------------------------------------------------------------
// Epilogue: blocks 0..7   -> per-batch affine scan -> bias (MUFU tanh)
//           blocks 8..263 -> memred = plain sum, one warp per output float4
// ---------------------------------------------------------------------------
__global__ void __launch_bounds__(256) epilogue_kernel(const int* __restrict__ pad,
                                                       const int* __restrict__ upd,
                                                       float* __restrict__ out) {
    const int tid = threadIdx.x;
    const int warp = tid >> 5;
    const int lane = tid & 31;

    if (blockIdx.x < Bv) {
        // ---------------- scan: u_t = c_t*u_{t-1} + eps*g_t*y_t ----------
        const int b = blockIdx.x;
        __shared__ float sWA[8], sWC[8], sWAe[8];

        bool gv[16]; bool pvb[16]; float yv[16];
        const int4* p4 = (const int4*)(pad + b * Tv);
        const int4* u4 = (const int4*)(upd + b * Tv);
#pragma unroll
        for (int q = 0; q < 4; q++) {
            int4 a = __ldg(&p4[tid * 4 + q]);
            int4 c = __ldg(&u4[tid * 4 + q]);
            int pa[4] = {a.x, a.y, a.z, a.w};
            int ua[4] = {c.x, c.y, c.z, c.w};
            float4 yq = *((const float4*)&d_y[b * Tv + tid * 16 + q * 4]);
            float ya[4] = {yq.x, yq.y, yq.z, yq.w};
#pragma unroll
            for (int r = 0; r < 4; r++) {
                pvb[q * 4 + r] = (pa[r] != 0);
                gv[q * 4 + r] = (pa[r] == 0) && (ua[r] != 0);
                yv[q * 4 + r] = ya[r];
            }
        }

        float C = 1.f, A = 0.f;
#pragma unroll
        for (int k = 0; k < 16; k++) {
            if (gv[k]) { A = 0.99f * A + 0.01f * yv[k]; C *= 0.99f; }
        }
#pragma unroll
        for (int off = 1; off < 32; off <<= 1) {
            float pC = __shfl_up_sync(0xffffffffu, C, off);
            float pA = __shfl_up_sync(0xffffffffu, A, off);
            float nA = fmaf(C, pA, A);
            float nC = C * pC;
            if (lane >= off) { A = nA; C = nC; }
        }
        float eC = __shfl_up_sync(0xffffffffu, C, 1);
        float eA = __shfl_up_sync(0xffffffffu, A, 1);
        if (lane == 0) { eC = 1.f; eA = 0.f; }
        if (lane == 31) { sWC[warp] = C; sWA[warp] = A; }
        __syncthreads();
        if (tid == 0) {
            float c = 1.f, a = 0.f;
#pragma unroll
            for (int ww = 0; ww < 8; ww++) {
                sWAe[ww] = a;
                float na = fmaf(sWC[ww], a, sWA[ww]);
                c = sWC[ww] * c; a = na;
            }
        }
        __syncthreads();

        float u = fmaf(eC, sWAe[warp], eA);
        float ob[16];
#pragma unroll
        for (int k = 0; k < 16; k++) {
            if (gv[k]) u = fmaf(0.99f, u, 0.01f * yv[k]);
            if (pvb[k]) {
                ob[k] = 1.0f;
            } else {
                // 1 + tanh(u) = 2 / (1 + e^(-2u)); MUFU path, rel err ~1e-6
                float bb = __fdividef(2.0f, 1.0f + __expf(-2.0f * u));
                ob[k] = fminf(fmaxf(bb, 0.8f), 1.2f);
            }
        }
        float4* o4 = (float4*)(out + b * Tv + tid * 16);
#pragma unroll
        for (int q = 0; q < 4; q++)
            o4[q] = make_float4(ob[q * 4], ob[q * 4 + 1], ob[q * 4 + 2], ob[q * 4 + 3]);
    } else {
        // ---------------- memred: plain sum, one warp per output float4 -----
        const int blk = blockIdx.x - Bv;        // 0..255
        const int o4 = blk * 8 + warp;          // float4 index over B*D (0..2047)
        const int b = o4 >> 8;                  // 256 float4 per batch
        const int d4 = o4 & 255;

        const float4* mp4 = (const float4*)&d_mempart[(size_t)b * TILES * Dv];
        float4 va = mp4[(size_t)lane * 256 + d4];
        float4 vb = mp4[(size_t)(lane + 32) * 256 + d4];
        float4 s;
        s.x = va.x + vb.x; s.y = va.y + vb.y;
        s.z = va.z + vb.z; s.w = va.w + vb.w;
#pragma unroll
        for (int off = 16; off; off >>= 1) {
            s.x += __shfl_down_sync(0xffffffffu, s.x, off);
            s.y += __shfl_down_sync(0xffffffffu, s.y, off);
            s.z += __shfl_down_sync(0xffffffffu, s.z, off);
            s.w += __shfl_down_sync(0xffffffffu, s.w, off);
        }
        if (lane == 0)
            ((float4*)(out + Bv * Tv))[o4] = s;
    }
}

// ---------------------------------------------------------------------------
extern "C" void kernel_launch(void* const* d_in, const int* in_sizes, int n_in,
                              void* d_out, int out_size) {
    const float* x = (const float*)d_in[0];            // write_signal (8,4096,1024)
    const int* pad = (const int*)d_in[1];              // pad_mask bool -> int32 (8,4096)
    const int* upd = (const int*)d_in[2];              // update_mask bool -> int32 (8,4096)
    const float* w = (const float*)d_in[3];            // w (1024,)
    float* out = (float*)d_out;                        // [bias (8*4096) | memory (8*1024)]

    dim3 grid(TILES, Bv);
    main_kernel<<<grid, 256>>>(x, w, pad, upd);
    epilogue_kernel<<<Bv + 256, 256>>>(pad, upd, out);
}